// round 5
// baseline (speedup 1.0000x reference)
#include <cuda_runtime.h>
#include <cstdint>

#define B_   16
#define C_   256
#define H_   56
#define W_   56
#define PH2  66     // padded rows: 5 + 56 + 5
#define PW2  74     // padded cols: 5 + 56 + 5 + 8 (x tile padded to 64)

// ---------------- static device scratch (no runtime allocation) ----------------
// activations as s8 {+1:0x01, -1:0xFF, 0:0x00}, layout [g][b][py][px][64]
__device__ __align__(16) unsigned char g_apk[(size_t)4 * B_ * PH2 * PW2 * 64];
// weights as s8 {+1,-1}, layout [br][g][n(64)][k(576)]
__device__ __align__(16) unsigned char g_wB[3][4][64 * 576];
__device__ float4 g_pp[3][C_];   // {scale, cb-mv1, alpha, mv2} per [branch][outch]

// ---------------- PTX wrappers (compute_103-safe: sm_80-era instructions) ------
__device__ __forceinline__ uint32_t smem_to_u32(const void* p) {
    uint32_t a;
    asm("{ .reg .u64 t; cvta.to.shared.u64 t, %1; cvt.u32.u64 %0, t; }" : "=r"(a) : "l"(p));
    return a;
}
#define LDSM4(r, addr) \
    asm volatile("ldmatrix.sync.aligned.m8n8.x4.shared.b16 {%0,%1,%2,%3}, [%4];" \
                 : "=r"((r)[0]), "=r"((r)[1]), "=r"((r)[2]), "=r"((r)[3]) : "r"(addr))
#define MMA_S8(d, a0, a1, a2, a3, b0, b1) \
    asm volatile("mma.sync.aligned.m16n8k32.row.col.s32.s8.s8.s32 " \
                 "{%0,%1,%2,%3}, {%4,%5,%6,%7}, {%8,%9}, {%0,%1,%2,%3};" \
                 : "+r"((d)[0]), "+r"((d)[1]), "+r"((d)[2]), "+r"((d)[3]) \
                 : "r"(a0), "r"(a1), "r"(a2), "r"(a3), "r"(b0), "r"(b1))

// ---------------- smem layout for main kernel ----------------------------------
#define RES_OFF 0                      // float res[112][264]
#define ACT_OFF 118272                 // s8 act[12][74][80]  (px pitch 80 -> LDSM conflict-free)
#define BS_OFF  189312                 // s8 B[64][592]       (row pitch 592 -> conflict-free)
#define GB_OFF  227200                 // float gamma[256], beta[256]
#define PP_OFF  229248                 // float4 pp[64] (params for current (br,g))
#define SMEM_TOT 230272

// ---------------------------------------------------------------------------
// Pack: x + bias -> s8 sign bytes in padded [g][b][py][px][64]
// ---------------------------------------------------------------------------
__global__ void pack_kernel(const float* __restrict__ x, const float* __restrict__ bias) {
    const int py   = blockIdx.x;                 // 0..65
    const int b    = blockIdx.y;
    const int g    = threadIdx.x >> 5;           // 4 warps = 4 groups
    const int lane = threadIdx.x & 31;
    const int yy   = py - 5;
    const bool rowin = (yy >= 0) && (yy < H_);

    for (int px0 = 0; px0 < PW2; px0 += 32) {
        int px = px0 + lane;
        if (px >= PW2) continue;
        int xx = px - 5;
        bool in = rowin && (xx >= 0) && (xx < W_);
        unsigned int wb[16] = {0};
        if (in) {
            const float* xp = x + (((size_t)b * C_ + g * 64) * H_ + yy) * W_ + xx;
            const float* bp = bias + g * 64;
            #pragma unroll
            for (int c = 0; c < 64; c++) {
                float v = __ldg(xp + (size_t)c * (H_ * W_)) + __ldg(bp + c);
                unsigned int byte = (v > 0.0f) ? 0x01u : ((v < 0.0f) ? 0xFFu : 0x00u);
                wb[c >> 2] |= byte << ((c & 3) * 8);
            }
        }
        uint4* dst = (uint4*)(g_apk + ((((size_t)g * B_ + b) * PH2 + py) * PW2 + px) * 64);
        dst[0] = make_uint4(wb[0],  wb[1],  wb[2],  wb[3]);
        dst[1] = make_uint4(wb[4],  wb[5],  wb[6],  wb[7]);
        dst[2] = make_uint4(wb[8],  wb[9],  wb[10], wb[11]);
        dst[3] = make_uint4(wb[12], wb[13], wb[14], wb[15]);
    }
}

// ---------------------------------------------------------------------------
// Weight prep: binarize vs per-outch mean; emit s8 rows [n][k=tap*64+c] + params
// ---------------------------------------------------------------------------
__global__ void wprep_kernel(const float* __restrict__ w, const float* __restrict__ cb,
                             const float* __restrict__ mv1, const float* __restrict__ alpha,
                             const float* __restrict__ mv2) {
    int o  = blockIdx.x;   // out channel 0..255
    int br = blockIdx.y;   // branch 0..2
    int c  = threadIdx.x;  // in-channel 0..63
    int g  = o >> 6, n = o & 63;
    const float* wp = w + (((size_t)br * C_ + o) * 64 + c) * 9;
    float vals[9];
    float sum = 0.0f, asum = 0.0f;
    #pragma unroll
    for (int t = 0; t < 9; t++) { float v = wp[t]; vals[t] = v; sum += v; asum += fabsf(v); }

    __shared__ float s1[64], s2[64];
    s1[c] = sum; s2[c] = asum;
    __syncthreads();
    #pragma unroll
    for (int off = 32; off > 0; off >>= 1) {
        if (c < off) { s1[c] += s1[c + off]; s2[c] += s2[c + off]; }
        __syncthreads();
    }
    float mean = s1[0] * (1.0f / 576.0f);

    unsigned char* dst = g_wB[br][g] + n * 576;
    #pragma unroll
    for (int t = 0; t < 9; t++)
        dst[t * 64 + c] = (vals[t] > mean) ? 0x01 : 0xFF;
    if (c == 0) {
        int i = br * C_ + o;
        g_pp[br][o] = make_float4(s2[0] * (1.0f / 576.0f), cb[i] - mv1[i], alpha[i], mv2[i]);
    }
}

// ---------------------------------------------------------------------------
// Main kernel: M=128 spatial (2 rows x 64 x), N=64 per group, K=576 (9 taps).
// IMMA m16n8k32 implicit GEMM; RPReLU epilogue; smem stash; fused LayerNorm.
// ---------------------------------------------------------------------------
__global__ void __launch_bounds__(256, 1)
main_kernel(const float* __restrict__ gamma, const float* __restrict__ beta,
            float* __restrict__ out) {
    extern __shared__ char smem[];
    float*  res = (float*)(smem + RES_OFF);
    char*   act = smem + ACT_OFF;
    char*   bs  = smem + BS_OFF;
    float*  gb  = (float*)(smem + GB_OFF);
    float4* pp  = (float4*)(smem + PP_OFF);
    const uint32_t act_u = smem_to_u32(act);
    const uint32_t bs_u  = smem_to_u32(bs);

    const int tid  = threadIdx.x;
    const int wid  = tid >> 5;
    const int lane = tid & 31;
    const int y0   = blockIdx.x * 2;
    const int b    = blockIdx.y;

    gb[tid] = gamma[tid];
    gb[256 + tid] = beta[tid];

    // ldmatrix base addresses (per-lane):
    // A: mats = (rows0-7,k0-15),(rows8-15,k0-15),(rows0-7,k16-31),(rows8-15,k16-31)
    const int rowInTile = (lane & 7) + ((lane >> 3) & 1) * 8;
    const int khalfA    = lane >> 4;
    const int m   = wid * 16 + rowInTile;
    const int ryA = m >> 6, xmA = m & 63;
    const uint32_t aBase = act_u + (uint32_t)(((ryA + 5) * 74 + (xmA + 5)) * 80 + khalfA * 16);
    // B: mats = 4 khalves (64 k-bytes = 2 k32-steps) of one 8-wide n-tile
    const uint32_t bBase = bs_u + (uint32_t)((lane & 7) * 592 + (lane >> 3) * 16);

    float facc[8][4];

    for (int g = 0; g < 4; g++) {
        __syncthreads();   // prior iteration's smem reads complete
        // ---- stage activation window [12][74][80] for group g ----
        {
            const uint4* src = (const uint4*)(g_apk +
                ((((size_t)g * B_ + b) * PH2 + y0) * PW2) * 64);
            for (int idx = tid; idx < 888 * 4; idx += 256) {
                int i = idx & 3, seg = idx >> 2;
                int px = seg % 74, r = seg / 74;
                *(uint4*)(act + (r * 74 + px) * 80 + i * 16) = src[(size_t)(r * 74 + px) * 4 + i];
            }
        }
        for (int br = 0; br < 3; br++) {
            if (br) __syncthreads();
            // ---- stage B [64][592] + params ----
            {
                const uint4* srcB = (const uint4*)(g_wB[br][g]);
                for (int idx = tid; idx < 64 * 36; idx += 256) {
                    int n = idx / 36, q = idx % 36;
                    *(uint4*)(bs + n * 592 + q * 16) = srcB[idx];
                }
                if (tid < 64) pp[tid] = ((const float4*)g_pp)[br * 256 + g * 64 + tid];
            }
            __syncthreads();

            const int dil = 2 * br + 1;
            uint32_t acc[8][4];
            #pragma unroll
            for (int nt = 0; nt < 8; nt++)
                #pragma unroll
                for (int i = 0; i < 4; i++) acc[nt][i] = 0u;

            #pragma unroll
            for (int tap = 0; tap < 9; tap++) {
                const int dy = (tap / 3 - 1) * dil;
                const int dx = (tap % 3 - 1) * dil;
                const uint32_t aA = aBase + (uint32_t)((dy * 74 + dx) * 80);
                uint32_t a0[4], a1[4];
                LDSM4(a0, aA);          // k-step 0 (bytes 0-31 of tap)
                LDSM4(a1, aA + 32);     // k-step 1 (bytes 32-63)
                const uint32_t bT = bBase + (uint32_t)(tap * 64);
                #pragma unroll
                for (int nt = 0; nt < 8; nt++) {
                    uint32_t bb[4];
                    LDSM4(bb, bT + (uint32_t)(nt * 8 * 592));
                    MMA_S8(acc[nt], a0[0], a0[1], a0[2], a0[3], bb[0], bb[1]);
                    MMA_S8(acc[nt], a1[0], a1[1], a1[2], a1[3], bb[2], bb[3]);
                }
            }

            // ---- per-branch epilogue: scale*dot + c0, RPReLU, + mv2 ----
            #pragma unroll
            for (int nt = 0; nt < 8; nt++) {
                const int ch0 = nt * 8 + 2 * (lane & 3);
                const float4 P0 = pp[ch0];
                const float4 P1 = pp[ch0 + 1];
                #pragma unroll
                for (int i = 0; i < 4; i++) {
                    const float4 P = (i & 1) ? P1 : P0;
                    float yv = P.x * (float)(int)acc[nt][i] + P.y;
                    yv = (yv >= 0.0f) ? yv : P.z * yv;
                    yv += P.w;
                    facc[nt][i] = (br == 0) ? yv : (facc[nt][i] + yv);
                }
            }
        }
        // ---- stash group result into res[pos][ch] (valid x only) ----
        {
            const int rowL = lane >> 2;
            const int chB  = g * 64 + 2 * (lane & 3);
            #pragma unroll
            for (int half = 0; half < 2; half++) {
                const int mC = wid * 16 + rowL + half * 8;
                const int ryC = mC >> 6, xC = mC & 63;
                if (xC < W_) {
                    float* rp = res + (size_t)(ryC * W_ + xC) * 264 + chB;
                    #pragma unroll
                    for (int nt = 0; nt < 8; nt++)
                        *(float2*)(rp + nt * 8) =
                            make_float2(facc[nt][half * 2], facc[nt][half * 2 + 1]);
                }
            }
        }
    }

    // ---- fused LayerNorm over 256 channels, coalesced output ----
    __syncthreads();
    if (tid < 112) {
        const float* rp = res + (size_t)tid * 264;
        float s = 0.0f, sq = 0.0f;
        #pragma unroll
        for (int c = 0; c < 256; c += 4) {
            float4 v = *(const float4*)(rp + c);
            s  += v.x + v.y + v.z + v.w;
            sq += v.x * v.x + v.y * v.y + v.z * v.z + v.w * v.w;
        }
        const float mean = s * (1.0f / 256.0f);
        const float rstd = rsqrtf(sq * (1.0f / 256.0f) - mean * mean + 1e-5f);
        const int yy = y0 + tid / W_, xx = tid % W_;
        float* op = out + (size_t)b * C_ * H_ * W_ + (size_t)yy * W_ + xx;
        #pragma unroll 8
        for (int c = 0; c < 256; c++)
            op[(size_t)c * (H_ * W_)] = (rp[c] - mean) * rstd * gb[c] + gb[256 + c];
    }
}

// ---------------------------------------------------------------------------
extern "C" void kernel_launch(void* const* d_in, const int* in_sizes, int n_in,
                              void* d_out, int out_size) {
    const float* x     = (const float*)d_in[0];
    const float* bias  = (const float*)d_in[1];
    const float* w     = (const float*)d_in[2];
    const float* cb    = (const float*)d_in[3];
    const float* mv1   = (const float*)d_in[4];
    const float* alpha = (const float*)d_in[5];
    const float* mv2   = (const float*)d_in[6];
    const float* gamma = (const float*)d_in[7];
    const float* beta  = (const float*)d_in[8];
    float* out = (float*)d_out;

    cudaFuncSetAttribute(main_kernel, cudaFuncAttributeMaxDynamicSharedMemorySize, SMEM_TOT);

    pack_kernel<<<dim3(PH2, B_), 128>>>(x, bias);
    wprep_kernel<<<dim3(C_, 3), 64>>>(w, cb, mv1, alpha, mv2);
    main_kernel<<<dim3(H_ / 2, B_), 256, SMEM_TOT>>>(gamma, beta, out);
}

// round 6
// speedup vs baseline: 1.0050x; 1.0050x over previous
#include <cuda_runtime.h>
#include <cstdint>

#define B_   16
#define C_   256
#define H_   56
#define W_   56
#define PH2  66     // padded rows: 5 + 56 + 5
#define PW2  74     // padded cols: 5 + 56 + 5 + 8 (x tile padded to 64)

// ---------------- static device scratch (no runtime allocation) ----------------
// activations as s8 {+1:0x01, -1:0xFF, 0:0x00}, layout [g][b][py][px][64]
__device__ __align__(16) unsigned char g_apk[(size_t)4 * B_ * PH2 * PW2 * 64];
// weights as s8 {+1,-1}, layout [br][g][n(64)][k(576)]
__device__ __align__(16) unsigned char g_wB[3][4][64 * 576];
__device__ float4 g_pp[3][C_];   // {scale, cb-mv1, alpha, mv2} per [branch][outch]

// ---------------- PTX wrappers (compute_103-safe: sm_80-era instructions) ------
__device__ __forceinline__ uint32_t smem_to_u32(const void* p) {
    uint32_t a;
    asm("{ .reg .u64 t; cvta.to.shared.u64 t, %1; cvt.u32.u64 %0, t; }" : "=r"(a) : "l"(p));
    return a;
}
#define LDSM4(r, addr) \
    asm volatile("ldmatrix.sync.aligned.m8n8.x4.shared.b16 {%0,%1,%2,%3}, [%4];" \
                 : "=r"((r)[0]), "=r"((r)[1]), "=r"((r)[2]), "=r"((r)[3]) : "r"(addr))
#define MMA_S8(d, a0, a1, a2, a3, b0, b1) \
    asm volatile("mma.sync.aligned.m16n8k32.row.col.s32.s8.s8.s32 " \
                 "{%0,%1,%2,%3}, {%4,%5,%6,%7}, {%8,%9}, {%0,%1,%2,%3};" \
                 : "+r"((d)[0]), "+r"((d)[1]), "+r"((d)[2]), "+r"((d)[3]) \
                 : "r"(a0), "r"(a1), "r"(a2), "r"(a3), "r"(b0), "r"(b1))

// ---------------- smem layout for main kernel ----------------------------------
#define RES_OFF 0                      // float res[112][264]
#define ACT_OFF 118272                 // s8 act[12][74][80]  (px pitch 80 -> LDSM conflict-free)
#define BS_OFF  189312                 // s8 B[64][592]       (row pitch 592 -> conflict-free)
#define GB_OFF  227200                 // float gamma[256], beta[256]
#define PP_OFF  229248                 // float4 pp[64] (params for current (br,g))
#define SMEM_TOT 230272

// ---------------------------------------------------------------------------
// Pack: x + bias -> s8 sign bytes in padded [g][b][py][px][64]
// ---------------------------------------------------------------------------
__global__ void pack_kernel(const float* __restrict__ x, const float* __restrict__ bias) {
    const int py   = blockIdx.x;                 // 0..65
    const int b    = blockIdx.y;
    const int g    = threadIdx.x >> 5;           // 4 warps = 4 groups
    const int lane = threadIdx.x & 31;
    const int yy   = py - 5;
    const bool rowin = (yy >= 0) && (yy < H_);

    for (int px0 = 0; px0 < PW2; px0 += 32) {
        int px = px0 + lane;
        if (px >= PW2) continue;
        int xx = px - 5;
        bool in = rowin && (xx >= 0) && (xx < W_);
        unsigned int wb[16] = {0};
        if (in) {
            const float* xp = x + (((size_t)b * C_ + g * 64) * H_ + yy) * W_ + xx;
            const float* bp = bias + g * 64;
            #pragma unroll
            for (int c = 0; c < 64; c++) {
                float v = __ldg(xp + (size_t)c * (H_ * W_)) + __ldg(bp + c);
                unsigned int byte = (v > 0.0f) ? 0x01u : ((v < 0.0f) ? 0xFFu : 0x00u);
                wb[c >> 2] |= byte << ((c & 3) * 8);
            }
        }
        uint4* dst = (uint4*)(g_apk + ((((size_t)g * B_ + b) * PH2 + py) * PW2 + px) * 64);
        dst[0] = make_uint4(wb[0],  wb[1],  wb[2],  wb[3]);
        dst[1] = make_uint4(wb[4],  wb[5],  wb[6],  wb[7]);
        dst[2] = make_uint4(wb[8],  wb[9],  wb[10], wb[11]);
        dst[3] = make_uint4(wb[12], wb[13], wb[14], wb[15]);
    }
}

// ---------------------------------------------------------------------------
// Weight prep: binarize vs per-outch mean; emit s8 rows [n][k=tap*64+c] + params
// ---------------------------------------------------------------------------
__global__ void wprep_kernel(const float* __restrict__ w, const float* __restrict__ cb,
                             const float* __restrict__ mv1, const float* __restrict__ alpha,
                             const float* __restrict__ mv2) {
    int o  = blockIdx.x;   // out channel 0..255
    int br = blockIdx.y;   // branch 0..2
    int c  = threadIdx.x;  // in-channel 0..63
    int g  = o >> 6, n = o & 63;
    const float* wp = w + (((size_t)br * C_ + o) * 64 + c) * 9;
    float vals[9];
    float sum = 0.0f, asum = 0.0f;
    #pragma unroll
    for (int t = 0; t < 9; t++) { float v = wp[t]; vals[t] = v; sum += v; asum += fabsf(v); }

    __shared__ float s1[64], s2[64];
    s1[c] = sum; s2[c] = asum;
    __syncthreads();
    #pragma unroll
    for (int off = 32; off > 0; off >>= 1) {
        if (c < off) { s1[c] += s1[c + off]; s2[c] += s2[c + off]; }
        __syncthreads();
    }
    float mean = s1[0] * (1.0f / 576.0f);

    unsigned char* dst = g_wB[br][g] + n * 576;
    #pragma unroll
    for (int t = 0; t < 9; t++)
        dst[t * 64 + c] = (vals[t] > mean) ? 0x01 : 0xFF;
    if (c == 0) {
        int i = br * C_ + o;
        g_pp[br][o] = make_float4(s2[0] * (1.0f / 576.0f), cb[i] - mv1[i], alpha[i], mv2[i]);
    }
}

// ---------------------------------------------------------------------------
// Main kernel: M=128 spatial (2 rows x 64 x), N=64 per group, K=576 (9 taps).
// IMMA m16n8k32 implicit GEMM; RPReLU epilogue; smem stash; fused LayerNorm.
// ---------------------------------------------------------------------------
__global__ void __launch_bounds__(256, 1)
main_kernel(const float* __restrict__ gamma, const float* __restrict__ beta,
            float* __restrict__ out) {
    extern __shared__ char smem[];
    float*  res = (float*)(smem + RES_OFF);
    char*   act = smem + ACT_OFF;
    char*   bs  = smem + BS_OFF;
    float*  gb  = (float*)(smem + GB_OFF);
    float4* pp  = (float4*)(smem + PP_OFF);
    const uint32_t act_u = smem_to_u32(act);
    const uint32_t bs_u  = smem_to_u32(bs);

    const int tid  = threadIdx.x;
    const int wid  = tid >> 5;
    const int lane = tid & 31;
    const int y0   = blockIdx.x * 2;
    const int b    = blockIdx.y;

    gb[tid] = gamma[tid];
    gb[256 + tid] = beta[tid];

    // ldmatrix base addresses (per-lane):
    // A: mats = (rows0-7,k0-15),(rows8-15,k0-15),(rows0-7,k16-31),(rows8-15,k16-31)
    const int rowInTile = (lane & 7) + ((lane >> 3) & 1) * 8;
    const int khalfA    = lane >> 4;
    const int m   = wid * 16 + rowInTile;
    const int ryA = m >> 6, xmA = m & 63;
    const uint32_t aBase = act_u + (uint32_t)(((ryA + 5) * 74 + (xmA + 5)) * 80 + khalfA * 16);
    // B: mats = 4 khalves (64 k-bytes = 2 k32-steps) of one 8-wide n-tile
    const uint32_t bBase = bs_u + (uint32_t)((lane & 7) * 592 + (lane >> 3) * 16);

    float facc[8][4];

    for (int g = 0; g < 4; g++) {
        __syncthreads();   // prior iteration's smem reads complete
        // ---- stage activation window [12][74][80] for group g ----
        {
            const uint4* src = (const uint4*)(g_apk +
                ((((size_t)g * B_ + b) * PH2 + y0) * PW2) * 64);
            for (int idx = tid; idx < 888 * 4; idx += 256) {
                int i = idx & 3, seg = idx >> 2;
                int px = seg % 74, r = seg / 74;
                *(uint4*)(act + (r * 74 + px) * 80 + i * 16) = src[(size_t)(r * 74 + px) * 4 + i];
            }
        }
        for (int br = 0; br < 3; br++) {
            if (br) __syncthreads();
            // ---- stage B [64][592] + params ----
            {
                const uint4* srcB = (const uint4*)(g_wB[br][g]);
                for (int idx = tid; idx < 64 * 36; idx += 256) {
                    int n = idx / 36, q = idx % 36;
                    *(uint4*)(bs + n * 592 + q * 16) = srcB[idx];
                }
                if (tid < 64) pp[tid] = ((const float4*)g_pp)[br * 256 + g * 64 + tid];
            }
            __syncthreads();

            const int dil = 2 * br + 1;
            uint32_t acc[8][4];
            #pragma unroll
            for (int nt = 0; nt < 8; nt++)
                #pragma unroll
                for (int i = 0; i < 4; i++) acc[nt][i] = 0u;

            #pragma unroll
            for (int tap = 0; tap < 9; tap++) {
                const int dy = (tap / 3 - 1) * dil;
                const int dx = (tap % 3 - 1) * dil;
                const uint32_t aA = aBase + (uint32_t)((dy * 74 + dx) * 80);
                uint32_t a0[4], a1[4];
                LDSM4(a0, aA);          // k-step 0 (bytes 0-31 of tap)
                LDSM4(a1, aA + 32);     // k-step 1 (bytes 32-63)
                const uint32_t bT = bBase + (uint32_t)(tap * 64);
                #pragma unroll
                for (int nt = 0; nt < 8; nt++) {
                    uint32_t bb[4];
                    LDSM4(bb, bT + (uint32_t)(nt * 8 * 592));
                    MMA_S8(acc[nt], a0[0], a0[1], a0[2], a0[3], bb[0], bb[1]);
                    MMA_S8(acc[nt], a1[0], a1[1], a1[2], a1[3], bb[2], bb[3]);
                }
            }

            // ---- per-branch epilogue: scale*dot + c0, RPReLU, + mv2 ----
            #pragma unroll
            for (int nt = 0; nt < 8; nt++) {
                const int ch0 = nt * 8 + 2 * (lane & 3);
                const float4 P0 = pp[ch0];
                const float4 P1 = pp[ch0 + 1];
                #pragma unroll
                for (int i = 0; i < 4; i++) {
                    const float4 P = (i & 1) ? P1 : P0;
                    float yv = P.x * (float)(int)acc[nt][i] + P.y;
                    yv = (yv >= 0.0f) ? yv : P.z * yv;
                    yv += P.w;
                    facc[nt][i] = (br == 0) ? yv : (facc[nt][i] + yv);
                }
            }
        }
        // ---- stash group result into res[pos][ch] (valid x only) ----
        {
            const int rowL = lane >> 2;
            const int chB  = g * 64 + 2 * (lane & 3);
            #pragma unroll
            for (int half = 0; half < 2; half++) {
                const int mC = wid * 16 + rowL + half * 8;
                const int ryC = mC >> 6, xC = mC & 63;
                if (xC < W_) {
                    float* rp = res + (size_t)(ryC * W_ + xC) * 264 + chB;
                    #pragma unroll
                    for (int nt = 0; nt < 8; nt++)
                        *(float2*)(rp + nt * 8) =
                            make_float2(facc[nt][half * 2], facc[nt][half * 2 + 1]);
                }
            }
        }
    }

    // ---- fused LayerNorm over 256 channels, coalesced output ----
    __syncthreads();
    if (tid < 112) {
        const float* rp = res + (size_t)tid * 264;
        float s = 0.0f, sq = 0.0f;
        #pragma unroll
        for (int c = 0; c < 256; c += 4) {
            float4 v = *(const float4*)(rp + c);
            s  += v.x + v.y + v.z + v.w;
            sq += v.x * v.x + v.y * v.y + v.z * v.z + v.w * v.w;
        }
        const float mean = s * (1.0f / 256.0f);
        const float rstd = rsqrtf(sq * (1.0f / 256.0f) - mean * mean + 1e-5f);
        const int yy = y0 + tid / W_, xx = tid % W_;
        float* op = out + (size_t)b * C_ * H_ * W_ + (size_t)yy * W_ + xx;
        #pragma unroll 8
        for (int c = 0; c < 256; c++)
            op[(size_t)c * (H_ * W_)] = (rp[c] - mean) * rstd * gb[c] + gb[256 + c];
    }
}

// ---------------------------------------------------------------------------
extern "C" void kernel_launch(void* const* d_in, const int* in_sizes, int n_in,
                              void* d_out, int out_size) {
    const float* x     = (const float*)d_in[0];
    const float* bias  = (const float*)d_in[1];
    const float* w     = (const float*)d_in[2];
    const float* cb    = (const float*)d_in[3];
    const float* mv1   = (const float*)d_in[4];
    const float* alpha = (const float*)d_in[5];
    const float* mv2   = (const float*)d_in[6];
    const float* gamma = (const float*)d_in[7];
    const float* beta  = (const float*)d_in[8];
    float* out = (float*)d_out;

    cudaFuncSetAttribute(main_kernel, cudaFuncAttributeMaxDynamicSharedMemorySize, SMEM_TOT);

    pack_kernel<<<dim3(PH2, B_), 128>>>(x, bias);
    wprep_kernel<<<dim3(C_, 3), 64>>>(w, cb, mv1, alpha, mv2);
    main_kernel<<<dim3(H_ / 2, B_), 256, SMEM_TOT>>>(gamma, beta, out);
}

// round 7
// speedup vs baseline: 1.0398x; 1.0346x over previous
#include <cuda_runtime.h>
#include <cstdint>

#define B_   16
#define C_   256
#define H_   56
#define W_   56
#define PH2  66     // padded rows: 5 + 56 + 5
#define PW2  74     // padded cols: 5 + 56 + 5 + 8

// ---------------- static device scratch (no runtime allocation) ----------------
__device__ __align__(16) unsigned char g_apk[(size_t)4 * B_ * PH2 * PW2 * 64]; // s8 acts
__device__ __align__(16) unsigned char g_wB[3][4][64 * 576];                   // s8 weights [br][g][n][k]
__device__ float4 g_pp[3][C_];                                 // {scale, cb-mv1, alpha, mv2}
__device__ __align__(16) float g_pre[(size_t)B_ * H_ * W_ * C_];               // pre-LN, [b][y][x][c]

// ---------------- PTX wrappers (compute_103-safe) ----------------
__device__ __forceinline__ uint32_t smem_to_u32(const void* p) {
    uint32_t a;
    asm("{ .reg .u64 t; cvta.to.shared.u64 t, %1; cvt.u32.u64 %0, t; }" : "=r"(a) : "l"(p));
    return a;
}
#define LDSM4(r, addr) \
    asm volatile("ldmatrix.sync.aligned.m8n8.x4.shared.b16 {%0,%1,%2,%3}, [%4];" \
                 : "=r"((r)[0]), "=r"((r)[1]), "=r"((r)[2]), "=r"((r)[3]) : "r"(addr))
#define MMA_S8(d, a0, a1, a2, a3, b0, b1) \
    asm volatile("mma.sync.aligned.m16n8k32.row.col.s32.s8.s8.s32 " \
                 "{%0,%1,%2,%3}, {%4,%5,%6,%7}, {%8,%9}, {%0,%1,%2,%3};" \
                 : "+r"((d)[0]), "+r"((d)[1]), "+r"((d)[2]), "+r"((d)[3]) \
                 : "r"(a0), "r"(a1), "r"(a2), "r"(a3), "r"(b0), "r"(b1))

// ---------------- conv kernel smem layout ----------------
#define ACT_OFF 0                      // s8 act[12][74][80] (pitch 80 -> LDSM conflict-free)
#define BS_OFF  71040                  // s8 B[64][592]
#define PP_OFF  108928                 // float4 pp[64]
#define CONV_SMEM 109952

// ---------------------------------------------------------------------------
// Pack: x + bias -> s8 {+1,-1,0} bytes, [g][b][py][px][64]. Thread = one
// 4-channel word at one px -> coalesced reads and contiguous writes.
// ---------------------------------------------------------------------------
__global__ void pack_kernel(const float* __restrict__ x, const float* __restrict__ bias) {
    const int tid = threadIdx.x;
    const int w   = tid & 15;          // channel-quad within group
    const int pxl = tid >> 4;
    const int px  = blockIdx.x * 16 + pxl;
    const int py  = blockIdx.y;
    const int b   = blockIdx.z >> 2;
    const int g   = blockIdx.z & 3;
    if (px >= PW2) return;
    const int yy = py - 5, xx = px - 5;
    unsigned int word = 0;
    if (yy >= 0 && yy < H_ && xx >= 0 && xx < W_) {
        const float* xp = x + (((size_t)b * C_ + g * 64 + w * 4) * H_ + yy) * W_ + xx;
        #pragma unroll
        for (int j = 0; j < 4; j++) {
            float v = __ldg(xp + (size_t)j * (H_ * W_)) + __ldg(bias + g * 64 + w * 4 + j);
            unsigned int byte = (v > 0.0f) ? 0x01u : ((v < 0.0f) ? 0xFFu : 0x00u);
            word |= byte << (j * 8);
        }
    }
    *(unsigned int*)(g_apk + ((((size_t)g * B_ + b) * PH2 + py) * PW2 + px) * 64 + w * 4) = word;
}

// ---------------------------------------------------------------------------
// Weight prep (unchanged): binarize vs per-outch mean, s8 rows [n][k] + params
// ---------------------------------------------------------------------------
__global__ void wprep_kernel(const float* __restrict__ w, const float* __restrict__ cb,
                             const float* __restrict__ mv1, const float* __restrict__ alpha,
                             const float* __restrict__ mv2) {
    int o  = blockIdx.x;
    int br = blockIdx.y;
    int c  = threadIdx.x;
    int g  = o >> 6, n = o & 63;
    const float* wp = w + (((size_t)br * C_ + o) * 64 + c) * 9;
    float vals[9];
    float sum = 0.0f, asum = 0.0f;
    #pragma unroll
    for (int t = 0; t < 9; t++) { float v = wp[t]; vals[t] = v; sum += v; asum += fabsf(v); }

    __shared__ float s1[64], s2[64];
    s1[c] = sum; s2[c] = asum;
    __syncthreads();
    #pragma unroll
    for (int off = 32; off > 0; off >>= 1) {
        if (c < off) { s1[c] += s1[c + off]; s2[c] += s2[c + off]; }
        __syncthreads();
    }
    float mean = s1[0] * (1.0f / 576.0f);

    unsigned char* dst = g_wB[br][g] + n * 576;
    #pragma unroll
    for (int t = 0; t < 9; t++)
        dst[t * 64 + c] = (vals[t] > mean) ? 0x01 : 0xFF;
    if (c == 0) {
        int i = br * C_ + o;
        g_pp[br][o] = make_float4(s2[0] * (1.0f / 576.0f), cb[i] - mv1[i], alpha[i], mv2[i]);
    }
}

// ---------------------------------------------------------------------------
// Conv kernel: block = (y-pair, batch, group). M=128 spatial x N=64 ch,
// K=576 over 9 taps x 2 k32. 3-branch loop with RPReLU accumulated in regs;
// writes pre-LN float to g_pre[b][y][x][c]. Occupancy 2.
// ---------------------------------------------------------------------------
__global__ void __launch_bounds__(256, 2)
conv_kernel() {
    extern __shared__ char smem[];
    char*   act = smem + ACT_OFF;
    char*   bs  = smem + BS_OFF;
    float4* pp  = (float4*)(smem + PP_OFF);
    const uint32_t act_u = smem_to_u32(act);
    const uint32_t bs_u  = smem_to_u32(bs);

    const int tid  = threadIdx.x;
    const int wid  = tid >> 5;
    const int lane = tid & 31;
    const int y0   = blockIdx.x * 2;
    const int b    = blockIdx.y;
    const int g    = blockIdx.z;

    // ---- stage activation window [12][74][80] for this group ----
    {
        const uint4* src = (const uint4*)(g_apk +
            ((((size_t)g * B_ + b) * PH2 + y0) * PW2) * 64);
        for (int idx = tid; idx < 888 * 4; idx += 256) {
            int i = idx & 3, seg = idx >> 2;
            int px = seg % 74, r = seg / 74;
            *(uint4*)(act + (r * 74 + px) * 80 + i * 16) = src[(size_t)seg * 4 + i];
        }
    }

    // ldmatrix per-lane base addresses (layouts verified in R6)
    const int rowInTile = (lane & 7) + ((lane >> 3) & 1) * 8;
    const int khalfA    = lane >> 4;
    const int m   = wid * 16 + rowInTile;
    const int ryA = m >> 6, xmA = m & 63;
    const uint32_t aBase = act_u + (uint32_t)(((ryA + 5) * 74 + (xmA + 5)) * 80 + khalfA * 16);
    const uint32_t bBase = bs_u + (uint32_t)((lane & 7) * 592 + (lane >> 3) * 16);

    float facc[8][4];

    #pragma unroll 1
    for (int br = 0; br < 3; br++) {
        if (br) __syncthreads();      // previous branch's B reads complete
        // ---- stage B [64][592] + params ----
        {
            const uint4* srcB = (const uint4*)(g_wB[br][g]);
            for (int idx = tid; idx < 64 * 36; idx += 256) {
                int n = idx / 36, q = idx % 36;
                *(uint4*)(bs + n * 592 + q * 16) = srcB[idx];
            }
            if (tid < 64) pp[tid] = ((const float4*)g_pp)[br * 256 + g * 64 + tid];
        }
        __syncthreads();

        const int dil = 2 * br + 1;
        uint32_t acc[8][4];
        #pragma unroll
        for (int nt = 0; nt < 8; nt++)
            #pragma unroll
            for (int i = 0; i < 4; i++) acc[nt][i] = 0u;

        #pragma unroll
        for (int tap = 0; tap < 9; tap++) {
            const int dy = (tap / 3 - 1) * dil;
            const int dx = (tap % 3 - 1) * dil;
            const uint32_t aA = aBase + (uint32_t)((dy * 74 + dx) * 80);
            uint32_t a0[4], a1[4];
            LDSM4(a0, aA);
            LDSM4(a1, aA + 32);
            const uint32_t bT = bBase + (uint32_t)(tap * 64);
            #pragma unroll
            for (int nt = 0; nt < 8; nt++) {
                uint32_t bb[4];
                LDSM4(bb, bT + (uint32_t)(nt * 8 * 592));
                MMA_S8(acc[nt], a0[0], a0[1], a0[2], a0[3], bb[0], bb[1]);
                MMA_S8(acc[nt], a1[0], a1[1], a1[2], a1[3], bb[2], bb[3]);
            }
        }

        // ---- epilogue: scale*dot + c0, RPReLU, + mv2, accumulate branches ----
        #pragma unroll
        for (int nt = 0; nt < 8; nt++) {
            const int ch0 = nt * 8 + 2 * (lane & 3);
            const float4 P0 = pp[ch0];
            const float4 P1 = pp[ch0 + 1];
            #pragma unroll
            for (int i = 0; i < 4; i++) {
                const float4 P = (i & 1) ? P1 : P0;
                float yv = P.x * (float)(int)acc[nt][i] + P.y;
                yv = (yv >= 0.0f) ? yv : P.z * yv;
                yv += P.w;
                facc[nt][i] = (br == 0) ? yv : (facc[nt][i] + yv);
            }
        }
    }

    // ---- write pre-LN to g_pre[b][y][x][ch] (32B-sector-aligned float2s) ----
    {
        const int rowL = lane >> 2;
        const int chB  = g * 64 + 2 * (lane & 3);
        #pragma unroll
        for (int half = 0; half < 2; half++) {
            const int mC = wid * 16 + rowL + half * 8;
            const int ryC = mC >> 6, xC = mC & 63;
            if (xC < W_) {
                float* p = g_pre + (((size_t)(b * H_ + y0 + ryC)) * W_ + xC) * 256 + chB;
                #pragma unroll
                for (int nt = 0; nt < 8; nt++)
                    *(float2*)(p + nt * 8) =
                        make_float2(facc[nt][half * 2], facc[nt][half * 2 + 1]);
            }
        }
    }
}

// ---------------------------------------------------------------------------
// LayerNorm kernel: block = (y, b). Coalesced load of [56][256], per-position
// stats via warp shuffles, transposed coalesced write to out[b][c][y][x].
// ---------------------------------------------------------------------------
#define LN_SMEM (56 * 257 * 4 + 56 * 2 * 4)
__global__ void __launch_bounds__(256)
ln_kernel(const float* __restrict__ gamma, const float* __restrict__ beta,
          float* __restrict__ out) {
    extern __shared__ float sm[];
    float* rs = sm;                    // [56][257]
    float* st = sm + 56 * 257;         // [56][2]
    const int y = blockIdx.x, b = blockIdx.y;
    const int tid = threadIdx.x;

    const float* src = g_pre + ((size_t)(b * H_ + y) * W_) * 256;
    for (int i = tid; i < 56 * 256; i += 256)
        rs[(i >> 8) * 257 + (i & 255)] = src[i];
    __syncthreads();

    {
        const int wid = tid >> 5, lane = tid & 31;
        #pragma unroll
        for (int q = 0; q < 7; q++) {
            const int xp = wid * 7 + q;
            float s = 0.0f, sq = 0.0f;
            #pragma unroll
            for (int k = 0; k < 8; k++) {
                float v = rs[xp * 257 + lane + 32 * k];
                s += v; sq += v * v;
            }
            #pragma unroll
            for (int off = 16; off > 0; off >>= 1) {
                s  += __shfl_down_sync(0xFFFFFFFFu, s,  off);
                sq += __shfl_down_sync(0xFFFFFFFFu, sq, off);
            }
            if (lane == 0) {
                float mean = s * (1.0f / 256.0f);
                st[xp * 2]     = mean;
                st[xp * 2 + 1] = rsqrtf(sq * (1.0f / 256.0f) - mean * mean + 1e-5f);
            }
        }
    }
    __syncthreads();

    if (tid < 224) {
        const int xw = tid % 56, cq = tid / 56;
        const float mean = st[xw * 2], rstd = st[xw * 2 + 1];
        #pragma unroll 4
        for (int co = 0; co < 64; co++) {
            const int ch = co * 4 + cq;
            out[(((size_t)b * C_ + ch) * H_ + y) * W_ + xw] =
                (rs[xw * 257 + ch] - mean) * rstd * __ldg(gamma + ch) + __ldg(beta + ch);
        }
    }
}

// ---------------------------------------------------------------------------
extern "C" void kernel_launch(void* const* d_in, const int* in_sizes, int n_in,
                              void* d_out, int out_size) {
    const float* x     = (const float*)d_in[0];
    const float* bias  = (const float*)d_in[1];
    const float* w     = (const float*)d_in[2];
    const float* cb    = (const float*)d_in[3];
    const float* mv1   = (const float*)d_in[4];
    const float* alpha = (const float*)d_in[5];
    const float* mv2   = (const float*)d_in[6];
    const float* gamma = (const float*)d_in[7];
    const float* beta  = (const float*)d_in[8];
    float* out = (float*)d_out;

    cudaFuncSetAttribute(conv_kernel, cudaFuncAttributeMaxDynamicSharedMemorySize, CONV_SMEM);
    cudaFuncSetAttribute(ln_kernel,   cudaFuncAttributeMaxDynamicSharedMemorySize, LN_SMEM);

    pack_kernel<<<dim3((PW2 + 15) / 16, PH2, B_ * 4), 256>>>(x, bias);
    wprep_kernel<<<dim3(C_, 3), 64>>>(w, cb, mv1, alpha, mv2);
    conv_kernel<<<dim3(H_ / 2, B_, 4), 256, CONV_SMEM>>>();
    ln_kernel<<<dim3(H_, B_), 256, LN_SMEM>>>(gamma, beta, out);
}

// round 8
// speedup vs baseline: 1.0967x; 1.0547x over previous
#include <cuda_runtime.h>
#include <cstdint>

#define B_   16
#define C_   256
#define H_   56
#define W_   56
#define PH2  66     // padded rows: 5 + 56 + 5
#define PW2  74     // padded cols: 5 + 56 + 5 + 8

// ---------------- static device scratch (no runtime allocation) ----------------
__device__ __align__(16) unsigned char g_apk[(size_t)4 * B_ * PH2 * PW2 * 64]; // s8 acts
__device__ __align__(16) unsigned char g_wB[3][4][64 * 576];                   // s8 weights [br][g][n][k]
__device__ float4 g_pp[3][C_];                                 // {scale, cb-mv1, alpha, mv2}
__device__ __align__(16) float g_pre[(size_t)B_ * H_ * W_ * C_];               // pre-LN, [b][y][x][c]

// ---------------- PTX wrappers (compute_103-safe) ----------------
__device__ __forceinline__ uint32_t smem_to_u32(const void* p) {
    uint32_t a;
    asm("{ .reg .u64 t; cvta.to.shared.u64 t, %1; cvt.u32.u64 %0, t; }" : "=r"(a) : "l"(p));
    return a;
}
#define LDSM4(r, addr) \
    asm volatile("ldmatrix.sync.aligned.m8n8.x4.shared.b16 {%0,%1,%2,%3}, [%4];" \
                 : "=r"((r)[0]), "=r"((r)[1]), "=r"((r)[2]), "=r"((r)[3]) : "r"(addr))
#define MMA_S8(d, a0, a1, a2, a3, b0, b1) \
    asm volatile("mma.sync.aligned.m16n8k32.row.col.s32.s8.s8.s32 " \
                 "{%0,%1,%2,%3}, {%4,%5,%6,%7}, {%8,%9}, {%0,%1,%2,%3};" \
                 : "+r"((d)[0]), "+r"((d)[1]), "+r"((d)[2]), "+r"((d)[3]) \
                 : "r"(a0), "r"(a1), "r"(a2), "r"(a3), "r"(b0), "r"(b1))

// ---------------- conv kernel smem layout ----------------
#define ACT_OFF 0                      // s8 act[12][74][80] (pitch 80 -> LDSM conflict-free)
#define BS_OFF  71040                  // s8 B[64][592]
#define PP_OFF  108928                 // float4 pp[64]
#define CONV_SMEM 109952

// ---------------------------------------------------------------------------
// Pack: x + bias -> s8 {+1,-1,0} bytes, [g][b][py][px][64]. Thread = one
// 4-channel word at one px -> coalesced reads and contiguous writes.
// ---------------------------------------------------------------------------
__global__ void pack_kernel(const float* __restrict__ x, const float* __restrict__ bias) {
    const int tid = threadIdx.x;
    const int w   = tid & 15;          // channel-quad within group
    const int pxl = tid >> 4;
    const int px  = blockIdx.x * 16 + pxl;
    const int py  = blockIdx.y;
    const int b   = blockIdx.z >> 2;
    const int g   = blockIdx.z & 3;
    if (px >= PW2) return;
    const int yy = py - 5, xx = px - 5;
    unsigned int word = 0;
    if (yy >= 0 && yy < H_ && xx >= 0 && xx < W_) {
        const float* xp = x + (((size_t)b * C_ + g * 64 + w * 4) * H_ + yy) * W_ + xx;
        #pragma unroll
        for (int j = 0; j < 4; j++) {
            float v = __ldg(xp + (size_t)j * (H_ * W_)) + __ldg(bias + g * 64 + w * 4 + j);
            unsigned int byte = (v > 0.0f) ? 0x01u : ((v < 0.0f) ? 0xFFu : 0x00u);
            word |= byte << (j * 8);
        }
    }
    *(unsigned int*)(g_apk + ((((size_t)g * B_ + b) * PH2 + py) * PW2 + px) * 64 + w * 4) = word;
}

// ---------------------------------------------------------------------------
// Weight prep (unchanged): binarize vs per-outch mean, s8 rows [n][k] + params
// ---------------------------------------------------------------------------
__global__ void wprep_kernel(const float* __restrict__ w, const float* __restrict__ cb,
                             const float* __restrict__ mv1, const float* __restrict__ alpha,
                             const float* __restrict__ mv2) {
    int o  = blockIdx.x;
    int br = blockIdx.y;
    int c  = threadIdx.x;
    int g  = o >> 6, n = o & 63;
    const float* wp = w + (((size_t)br * C_ + o) * 64 + c) * 9;
    float vals[9];
    float sum = 0.0f, asum = 0.0f;
    #pragma unroll
    for (int t = 0; t < 9; t++) { float v = wp[t]; vals[t] = v; sum += v; asum += fabsf(v); }

    __shared__ float s1[64], s2[64];
    s1[c] = sum; s2[c] = asum;
    __syncthreads();
    #pragma unroll
    for (int off = 32; off > 0; off >>= 1) {
        if (c < off) { s1[c] += s1[c + off]; s2[c] += s2[c + off]; }
        __syncthreads();
    }
    float mean = s1[0] * (1.0f / 576.0f);

    unsigned char* dst = g_wB[br][g] + n * 576;
    #pragma unroll
    for (int t = 0; t < 9; t++)
        dst[t * 64 + c] = (vals[t] > mean) ? 0x01 : 0xFF;
    if (c == 0) {
        int i = br * C_ + o;
        g_pp[br][o] = make_float4(s2[0] * (1.0f / 576.0f), cb[i] - mv1[i], alpha[i], mv2[i]);
    }
}

// ---------------------------------------------------------------------------
// Conv kernel: block = (y-pair, batch, group). M=128 spatial x N=64 ch,
// K=576 over 9 taps x 2 k32. 3-branch loop with RPReLU accumulated in regs;
// writes pre-LN float to g_pre[b][y][x][c]. Occupancy 2.
// ---------------------------------------------------------------------------
__global__ void __launch_bounds__(256, 2)
conv_kernel() {
    extern __shared__ char smem[];
    char*   act = smem + ACT_OFF;
    char*   bs  = smem + BS_OFF;
    float4* pp  = (float4*)(smem + PP_OFF);
    const uint32_t act_u = smem_to_u32(act);
    const uint32_t bs_u  = smem_to_u32(bs);

    const int tid  = threadIdx.x;
    const int wid  = tid >> 5;
    const int lane = tid & 31;
    const int y0   = blockIdx.x * 2;
    const int b    = blockIdx.y;
    const int g    = blockIdx.z;

    // ---- stage activation window [12][74][80] for this group ----
    {
        const uint4* src = (const uint4*)(g_apk +
            ((((size_t)g * B_ + b) * PH2 + y0) * PW2) * 64);
        for (int idx = tid; idx < 888 * 4; idx += 256) {
            int i = idx & 3, seg = idx >> 2;
            int px = seg % 74, r = seg / 74;
            *(uint4*)(act + (r * 74 + px) * 80 + i * 16) = src[(size_t)seg * 4 + i];
        }
    }

    // ldmatrix per-lane base addresses (layouts verified in R6)
    const int rowInTile = (lane & 7) + ((lane >> 3) & 1) * 8;
    const int khalfA    = lane >> 4;
    const int m   = wid * 16 + rowInTile;
    const int ryA = m >> 6, xmA = m & 63;
    const uint32_t aBase = act_u + (uint32_t)(((ryA + 5) * 74 + (xmA + 5)) * 80 + khalfA * 16);
    const uint32_t bBase = bs_u + (uint32_t)((lane & 7) * 592 + (lane >> 3) * 16);

    float facc[8][4];

    #pragma unroll 1
    for (int br = 0; br < 3; br++) {
        if (br) __syncthreads();      // previous branch's B reads complete
        // ---- stage B [64][592] + params ----
        {
            const uint4* srcB = (const uint4*)(g_wB[br][g]);
            for (int idx = tid; idx < 64 * 36; idx += 256) {
                int n = idx / 36, q = idx % 36;
                *(uint4*)(bs + n * 592 + q * 16) = srcB[idx];
            }
            if (tid < 64) pp[tid] = ((const float4*)g_pp)[br * 256 + g * 64 + tid];
        }
        __syncthreads();

        const int dil = 2 * br + 1;
        uint32_t acc[8][4];
        #pragma unroll
        for (int nt = 0; nt < 8; nt++)
            #pragma unroll
            for (int i = 0; i < 4; i++) acc[nt][i] = 0u;

        #pragma unroll
        for (int tap = 0; tap < 9; tap++) {
            const int dy = (tap / 3 - 1) * dil;
            const int dx = (tap % 3 - 1) * dil;
            const uint32_t aA = aBase + (uint32_t)((dy * 74 + dx) * 80);
            uint32_t a0[4], a1[4];
            LDSM4(a0, aA);
            LDSM4(a1, aA + 32);
            const uint32_t bT = bBase + (uint32_t)(tap * 64);
            #pragma unroll
            for (int nt = 0; nt < 8; nt++) {
                uint32_t bb[4];
                LDSM4(bb, bT + (uint32_t)(nt * 8 * 592));
                MMA_S8(acc[nt], a0[0], a0[1], a0[2], a0[3], bb[0], bb[1]);
                MMA_S8(acc[nt], a1[0], a1[1], a1[2], a1[3], bb[2], bb[3]);
            }
        }

        // ---- epilogue: scale*dot + c0, RPReLU, + mv2, accumulate branches ----
        #pragma unroll
        for (int nt = 0; nt < 8; nt++) {
            const int ch0 = nt * 8 + 2 * (lane & 3);
            const float4 P0 = pp[ch0];
            const float4 P1 = pp[ch0 + 1];
            #pragma unroll
            for (int i = 0; i < 4; i++) {
                const float4 P = (i & 1) ? P1 : P0;
                float yv = P.x * (float)(int)acc[nt][i] + P.y;
                yv = (yv >= 0.0f) ? yv : P.z * yv;
                yv += P.w;
                facc[nt][i] = (br == 0) ? yv : (facc[nt][i] + yv);
            }
        }
    }

    // ---- write pre-LN to g_pre[b][y][x][ch] (32B-sector-aligned float2s) ----
    {
        const int rowL = lane >> 2;
        const int chB  = g * 64 + 2 * (lane & 3);
        #pragma unroll
        for (int half = 0; half < 2; half++) {
            const int mC = wid * 16 + rowL + half * 8;
            const int ryC = mC >> 6, xC = mC & 63;
            if (xC < W_) {
                float* p = g_pre + (((size_t)(b * H_ + y0 + ryC)) * W_ + xC) * 256 + chB;
                #pragma unroll
                for (int nt = 0; nt < 8; nt++)
                    *(float2*)(p + nt * 8) =
                        make_float2(facc[nt][half * 2], facc[nt][half * 2 + 1]);
            }
        }
    }
}

// ---------------------------------------------------------------------------
// LayerNorm kernel: block = (y, b). Coalesced load of [56][256], per-position
// stats via warp shuffles, transposed coalesced write to out[b][c][y][x].
// ---------------------------------------------------------------------------
#define LN_SMEM (56 * 257 * 4 + 56 * 2 * 4)
__global__ void __launch_bounds__(256)
ln_kernel(const float* __restrict__ gamma, const float* __restrict__ beta,
          float* __restrict__ out) {
    extern __shared__ float sm[];
    float* rs = sm;                    // [56][257]
    float* st = sm + 56 * 257;         // [56][2]
    const int y = blockIdx.x, b = blockIdx.y;
    const int tid = threadIdx.x;

    const float* src = g_pre + ((size_t)(b * H_ + y) * W_) * 256;
    for (int i = tid; i < 56 * 256; i += 256)
        rs[(i >> 8) * 257 + (i & 255)] = src[i];
    __syncthreads();

    {
        const int wid = tid >> 5, lane = tid & 31;
        #pragma unroll
        for (int q = 0; q < 7; q++) {
            const int xp = wid * 7 + q;
            float s = 0.0f, sq = 0.0f;
            #pragma unroll
            for (int k = 0; k < 8; k++) {
                float v = rs[xp * 257 + lane + 32 * k];
                s += v; sq += v * v;
            }
            #pragma unroll
            for (int off = 16; off > 0; off >>= 1) {
                s  += __shfl_down_sync(0xFFFFFFFFu, s,  off);
                sq += __shfl_down_sync(0xFFFFFFFFu, sq, off);
            }
            if (lane == 0) {
                float mean = s * (1.0f / 256.0f);
                st[xp * 2]     = mean;
                st[xp * 2 + 1] = rsqrtf(sq * (1.0f / 256.0f) - mean * mean + 1e-5f);
            }
        }
    }
    __syncthreads();

    if (tid < 224) {
        const int xw = tid % 56, cq = tid / 56;
        const float mean = st[xw * 2], rstd = st[xw * 2 + 1];
        #pragma unroll 4
        for (int co = 0; co < 64; co++) {
            const int ch = co * 4 + cq;
            out[(((size_t)b * C_ + ch) * H_ + y) * W_ + xw] =
                (rs[xw * 257 + ch] - mean) * rstd * __ldg(gamma + ch) + __ldg(beta + ch);
        }
    }
}

// ---------------------------------------------------------------------------
extern "C" void kernel_launch(void* const* d_in, const int* in_sizes, int n_in,
                              void* d_out, int out_size) {
    const float* x     = (const float*)d_in[0];
    const float* bias  = (const float*)d_in[1];
    const float* w     = (const float*)d_in[2];
    const float* cb    = (const float*)d_in[3];
    const float* mv1   = (const float*)d_in[4];
    const float* alpha = (const float*)d_in[5];
    const float* mv2   = (const float*)d_in[6];
    const float* gamma = (const float*)d_in[7];
    const float* beta  = (const float*)d_in[8];
    float* out = (float*)d_out;

    cudaFuncSetAttribute(conv_kernel, cudaFuncAttributeMaxDynamicSharedMemorySize, CONV_SMEM);
    cudaFuncSetAttribute(ln_kernel,   cudaFuncAttributeMaxDynamicSharedMemorySize, LN_SMEM);

    pack_kernel<<<dim3((PW2 + 15) / 16, PH2, B_ * 4), 256>>>(x, bias);
    wprep_kernel<<<dim3(C_, 3), 64>>>(w, cb, mv1, alpha, mv2);
    conv_kernel<<<dim3(H_ / 2, B_, 4), 256, CONV_SMEM>>>();
    ln_kernel<<<dim3(H_, B_), 256, LN_SMEM>>>(gamma, beta, out);
}

// round 9
// speedup vs baseline: 2.3464x; 2.1395x over previous
#include <cuda_runtime.h>
#include <cstdint>

#define B_ 16
#define C_ 256
#define H_ 56
#define W_ 56
#define G_ 4
#define PAD_ 5
#define PH_ 66
#define PW_ 66
#define TW_ 8

// Scratch (static device globals — no allocation at runtime).
__device__ ulonglong2 g_pk[B_ * PH_ * PW_ * G_];          // (sign, nonzero) per (b,py,px,g)
__device__ unsigned long long g_wbits[3][9][C_];          // weight sign bits [branch][tap][outch]
__device__ float g_params[3][4][C_];                      // [branch][{scale, cb-move1, alpha, move2}][outch]

// ---- single-LOP3 helpers ----
__device__ __forceinline__ uint32_t lop3_xor3(uint32_t a, uint32_t b, uint32_t c) { // a^b^c
    uint32_t r; asm("lop3.b32 %0, %1, %2, %3, 0x96;" : "=r"(r) : "r"(a), "r"(b), "r"(c)); return r;
}
__device__ __forceinline__ uint32_t lop3_maj(uint32_t a, uint32_t b, uint32_t c) {  // majority
    uint32_t r; asm("lop3.b32 %0, %1, %2, %3, 0xE8;" : "=r"(r) : "r"(a), "r"(b), "r"(c)); return r;
}
__device__ __forceinline__ uint32_t lop3_mask(uint32_t nz, uint32_t s, uint32_t w) { // nz & (s^w)
    uint32_t r; asm("lop3.b32 %0, %1, %2, %3, 0x60;" : "=r"(r) : "r"(nz), "r"(s), "r"(w)); return r;
}

// ---------------------------------------------------------------------------
// Pack activations (coalesced, from R3): warp = one group, lanes = consecutive x.
// ---------------------------------------------------------------------------
__global__ void pack_kernel(const float* __restrict__ x, const float* __restrict__ bias) {
    const int py   = blockIdx.x;
    const int b    = blockIdx.y;
    const int g    = threadIdx.x >> 5;     // 4 warps = 4 groups
    const int lane = threadIdx.x & 31;
    const int yy   = py - PAD_;
    const bool rowin = (yy >= 0) && (yy < H_);
    const float* bp = bias + g * 64;

    #pragma unroll
    for (int px0 = 0; px0 < PW_; px0 += 32) {
        int px = px0 + lane;
        int xx = px - PAD_;
        bool in = rowin && (xx >= 0) && (xx < W_) && (px < PW_);
        unsigned long long s = 0ull, nz = 0ull;
        if (in) {
            const float* xp = x + (((size_t)b * C_ + g * 64) * H_ + yy) * W_ + xx;
            #pragma unroll
            for (int c = 0; c < 64; c++) {
                float v = __ldg(xp + (size_t)c * (H_ * W_)) + __ldg(bp + c);
                s  |= (unsigned long long)(v > 0.0f)  << c;
                nz |= (unsigned long long)(v != 0.0f) << c;
            }
        }
        if (px < PW_)
            g_pk[(((size_t)b * PH_ + py) * PW_ + px) * G_ + g] = make_ulonglong2(s, nz);
    }
}

// ---------------------------------------------------------------------------
// Weight prep: per (branch, outch): mean|w|, sign bits per tap, fused params.
// ---------------------------------------------------------------------------
__global__ void wprep_kernel(const float* __restrict__ w, const float* __restrict__ cb,
                             const float* __restrict__ mv1, const float* __restrict__ alpha,
                             const float* __restrict__ mv2) {
    int o  = blockIdx.x;   // 0..255
    int br = blockIdx.y;   // 0..2
    int c  = threadIdx.x;  // 0..63
    const float* wp = w + (((size_t)br * C_ + o) * 64 + c) * 9;
    float vals[9];
    float sum = 0.0f, asum = 0.0f;
    #pragma unroll
    for (int t = 0; t < 9; t++) { float v = wp[t]; vals[t] = v; sum += v; asum += fabsf(v); }

    __shared__ float s1[64], s2[64];
    s1[c] = sum; s2[c] = asum;
    __syncthreads();
    #pragma unroll
    for (int off = 32; off > 0; off >>= 1) {
        if (c < off) { s1[c] += s1[c + off]; s2[c] += s2[c + off]; }
        __syncthreads();
    }
    float mean = s1[0] * (1.0f / 576.0f);

    __shared__ unsigned int bits[9][2];
    #pragma unroll
    for (int t = 0; t < 9; t++) {
        unsigned bm = __ballot_sync(0xFFFFFFFFu, vals[t] > mean);
        if ((c & 31) == 0) bits[t][c >> 5] = bm;
    }
    __syncthreads();
    if (c < 9)
        g_wbits[br][c][o] = ((unsigned long long)bits[c][1] << 32) | (unsigned long long)bits[c][0];
    if (c == 0) {
        int i = br * C_ + o;
        g_params[br][0][o] = s2[0] * (1.0f / 576.0f);   // scale = mean|w|
        g_params[br][1][o] = cb[i] - mv1[i];            // fused conv-bias - move1
        g_params[br][2][o] = alpha[i];
        g_params[br][3][o] = mv2[i];
    }
}

// ---------------------------------------------------------------------------
// Main kernel: one block = (b, y, 8 x), 256 threads = 256 out channels.
// XNOR conv with CSA-compressed popcounts (8 POPC per branch-pos instead of 18),
// fused RPReLU + branch sum + channel LayerNorm.
// ---------------------------------------------------------------------------
__global__ void __launch_bounds__(256, 2)
main_kernel(const float* __restrict__ gamma, const float* __restrict__ beta,
            float* __restrict__ out) {
    const int x0 = blockIdx.x * TW_;
    const int y  = blockIdx.y;
    const int b  = blockIdx.z;
    const int o  = threadIdx.x;
    const int g  = o >> 6;

    __shared__ uint4 tile[7 * 18 * 4];   // {s_lo, s_hi, nz_lo, nz_hi} per (row,col,group)
    __shared__ int pzs[3][4][TW_];       // sum of popc(nz) over 9 taps
    __shared__ float redbuf[TW_][256];
    __shared__ float stats[TW_][2];

    // ---- load tile ----
    const int rowoff[7] = {-5, -3, -1, 0, 1, 3, 5};
    for (int e = o; e < 7 * 18 * 4; e += 256) {
        int gg  = e & 3;
        int q   = e >> 2;
        int col = q % 18;
        int r   = q / 18;
        int py  = y + rowoff[r] + PAD_;
        int px  = x0 + col;
        tile[e] = ((const uint4*)g_pk)[(((size_t)b * PH_ + py) * PW_ + px) * G_ + gg];
    }
    __syncthreads();

    // ---- per-(branch,group,x) sum of popc(nz) over 9 taps ----
    if (o < 96) {
        int br = o / 32, rem = o % 32;
        int gg = rem >> 3, p = rem & 7;
        int d = 2 * br + 1;
        int s = 0;
        #pragma unroll
        for (int ky = 0; ky < 3; ky++) {
            int ridx = 3 + (ky - 1) * (br + 1);
            #pragma unroll
            for (int kx = 0; kx < 3; kx++) {
                int col = 5 + p + (kx - 1) * d;
                const uint4 v = tile[(ridx * 18 + col) * 4 + gg];
                s += __popc(v.z) + __popc(v.w);
            }
        }
        pzs[br][gg][p] = s;
    }
    __syncthreads();

    // ---- XNOR conv with CSA popcount, 3 branches, fused RPReLU ----
    float outv[TW_];
    {
        float m2s = g_params[0][3][o] + g_params[1][3][o] + g_params[2][3][o];
        #pragma unroll
        for (int p = 0; p < TW_; p++) outv[p] = m2s;
    }

    const uint4* tg = tile + g;

    #pragma unroll
    for (int br = 0; br < 3; br++) {
        const int d = 2 * br + 1;
        uint32_t wlo[9], whi[9];
        #pragma unroll
        for (int t = 0; t < 9; t++) {
            unsigned long long wq = g_wbits[br][t][o];
            wlo[t] = (uint32_t)wq;
            whi[t] = (uint32_t)(wq >> 32);
        }
        const float scl = g_params[br][0][o];
        const float c0  = g_params[br][1][o];
        const float al  = g_params[br][2][o];
        #pragma unroll
        for (int p = 0; p < TW_; p++) {
            // masks: m = nz & (s ^ w), one LOP3 per 32-bit half per tap
            uint32_t ml[9], mh[9];
            #pragma unroll
            for (int ky = 0; ky < 3; ky++) {
                const int ridx = 3 + (ky - 1) * (br + 1);
                #pragma unroll
                for (int kx = 0; kx < 3; kx++) {
                    const int col = 5 + p + (kx - 1) * d;
                    const uint4 v = tg[(ridx * 18 + col) * 4];
                    const int t = ky * 3 + kx;
                    ml[t] = lop3_mask(v.z, v.x, wlo[t]);
                    mh[t] = lop3_mask(v.w, v.y, whi[t]);
                }
            }
            // CSA level 1: 3 FAs per half (taps 0-2, 3-5, 6-8)
            uint32_t sl0 = lop3_xor3(ml[0], ml[1], ml[2]), cl0 = lop3_maj(ml[0], ml[1], ml[2]);
            uint32_t sl1 = lop3_xor3(ml[3], ml[4], ml[5]), cl1 = lop3_maj(ml[3], ml[4], ml[5]);
            uint32_t sl2 = lop3_xor3(ml[6], ml[7], ml[8]), cl2 = lop3_maj(ml[6], ml[7], ml[8]);
            uint32_t sh0 = lop3_xor3(mh[0], mh[1], mh[2]), ch0 = lop3_maj(mh[0], mh[1], mh[2]);
            uint32_t sh1 = lop3_xor3(mh[3], mh[4], mh[5]), ch1 = lop3_maj(mh[3], mh[4], mh[5]);
            uint32_t sh2 = lop3_xor3(mh[6], mh[7], mh[8]), ch2 = lop3_maj(mh[6], mh[7], mh[8]);
            // CSA level 2: FA over the s-words (wt1) and over the c-words (wt2)
            uint32_t Sl  = lop3_xor3(sl0, sl1, sl2), C2la = lop3_maj(sl0, sl1, sl2);
            uint32_t S2l = lop3_xor3(cl0, cl1, cl2), C4l  = lop3_maj(cl0, cl1, cl2);
            uint32_t Sh  = lop3_xor3(sh0, sh1, sh2), C2ha = lop3_maj(sh0, sh1, sh2);
            uint32_t S2h = lop3_xor3(ch0, ch1, ch2), C4h  = lop3_maj(ch0, ch1, ch2);
            // dsum = popc(S) + 2*(popc(C2)+popc(S2)) + 4*popc(C4), summed over halves
            int w1 = __popc(Sl) + __popc(Sh);
            int w2 = __popc(C2la) + __popc(S2l) + __popc(C2ha) + __popc(S2h);
            int w4 = __popc(C4l) + __popc(C4h);
            int dsum = w1 + 2 * w2 + 4 * w4;
            int dot  = pzs[br][g][p] - 2 * dsum;   // integer-exact +/-1 dot product
            float yv = scl * (float)dot + c0;
            yv = (yv >= 0.0f) ? yv : al * yv;      // RPReLU core
            outv[p] += yv;
        }
    }

    // ---- fused LayerNorm over channels ----
    #pragma unroll
    for (int p = 0; p < TW_; p++) redbuf[p][o] = outv[p];
    __syncthreads();
    {
        int wid = o >> 5, lane = o & 31;  // 8 warps, warp w reduces position w
        float s = 0.0f, sq = 0.0f;
        #pragma unroll
        for (int k = 0; k < 8; k++) {
            float v = redbuf[wid][lane + 32 * k];
            s += v; sq += v * v;
        }
        #pragma unroll
        for (int off = 16; off > 0; off >>= 1) {
            s  += __shfl_down_sync(0xFFFFFFFFu, s,  off);
            sq += __shfl_down_sync(0xFFFFFFFFu, sq, off);
        }
        if (lane == 0) {
            float mean = s * (1.0f / 256.0f);
            float var  = sq * (1.0f / 256.0f) - mean * mean;
            stats[wid][0] = mean;
            stats[wid][1] = rsqrtf(var + 1e-5f);
        }
    }
    __syncthreads();

    float gm = gamma[o], bt = beta[o];
    float res[TW_];
    #pragma unroll
    for (int p = 0; p < TW_; p++)
        res[p] = (outv[p] - stats[p][0]) * stats[p][1] * gm + bt;

    float4* op = (float4*)(out + (((size_t)b * C_ + o) * H_ + y) * W_ + x0);
    op[0] = make_float4(res[0], res[1], res[2], res[3]);
    op[1] = make_float4(res[4], res[5], res[6], res[7]);
}

// ---------------------------------------------------------------------------
extern "C" void kernel_launch(void* const* d_in, const int* in_sizes, int n_in,
                              void* d_out, int out_size) {
    const float* x     = (const float*)d_in[0];
    const float* bias  = (const float*)d_in[1];
    const float* w     = (const float*)d_in[2];
    const float* cb    = (const float*)d_in[3];
    const float* mv1   = (const float*)d_in[4];
    const float* alpha = (const float*)d_in[5];
    const float* mv2   = (const float*)d_in[6];
    const float* gamma = (const float*)d_in[7];
    const float* beta  = (const float*)d_in[8];
    float* out = (float*)d_out;

    pack_kernel<<<dim3(PH_, B_), 128>>>(x, bias);
    wprep_kernel<<<dim3(C_, 3), 64>>>(w, cb, mv1, alpha, mv2);
    main_kernel<<<dim3(W_ / TW_, H_, B_), 256>>>(gamma, beta, out);
}